// round 14
// baseline (speedup 1.0000x reference)
#include <cuda_runtime.h>
#include <cuda_bf16.h>
#include <cuda_fp16.h>
#include <math.h>
#include <stdint.h>

#define TPB   512
#define MT    128
#define DIN   512
#define HH    50
#define DOUT  128
#define MAXN  0.996f
#define MINN  1e-15f

typedef unsigned long long ull;
typedef uint32_t u32;

// ---- smem byte offsets ----
#define OFF_W1R   0          // W1 fp16 resident: 64 rows x 1040B (512 fp16 + 16B pad)
#define OFF_W3H   66560      // W3 hi 128x144 (resident)
#define OFF_W3L   84992
#define OFF_UH    103424     // u bf16 hi 128x144
#define OFF_UL    121856
#define OFF_RED   140288     // 1024 f32 exchange
#define OFF_HB1   144384     // 64 f32
#define OFF_HB3   144640     // 128 f32
#define OFF_X2S   145152     // 128 f32
#define OFF_UNS   145664     // 128 f32
#define SMEM_BYTES 146176

__device__ float g_hb1[64];
__device__ float g_hb3[128];
__device__ float g_hb1sq, g_hb3sq;
__device__ __align__(16) __half g_w1f[64 * 512];          // fp16 W1, rows 50..63 zero
__device__ __align__(16) __nv_bfloat16 g_w3h[128 * 64];   // k 50..63 zero
__device__ __align__(16) __nv_bfloat16 g_w3l[128 * 64];

__device__ __forceinline__ float artanh_c(float z) {
    z = fminf(z, 1.0f - 1e-7f);
    return 0.5f * logf((1.0f + z) / (1.0f - z));
}

// ---- MMA / async helpers ----
__device__ __forceinline__ void mma_f16(float* d, const u32* a, const u32* b) {
    asm("mma.sync.aligned.m16n8k16.row.col.f32.f16.f16.f32 "
        "{%0,%1,%2,%3}, {%4,%5,%6,%7}, {%8,%9}, {%0,%1,%2,%3};"
        : "+f"(d[0]), "+f"(d[1]), "+f"(d[2]), "+f"(d[3])
        : "r"(a[0]), "r"(a[1]), "r"(a[2]), "r"(a[3]), "r"(b[0]), "r"(b[1]));
}
__device__ __forceinline__ void mma_bf16(float* d, const u32* a, const u32* b) {
    asm("mma.sync.aligned.m16n8k16.row.col.f32.bf16.bf16.f32 "
        "{%0,%1,%2,%3}, {%4,%5,%6,%7}, {%8,%9}, {%0,%1,%2,%3};"
        : "+f"(d[0]), "+f"(d[1]), "+f"(d[2]), "+f"(d[3])
        : "r"(a[0]), "r"(a[1]), "r"(a[2]), "r"(a[3]), "r"(b[0]), "r"(b[1]));
}
__device__ __forceinline__ void ldsm4(u32* r, u32 addr) {
    asm volatile("ldmatrix.sync.aligned.m8n8.x4.shared.b16 {%0,%1,%2,%3}, [%4];"
        : "=r"(r[0]), "=r"(r[1]), "=r"(r[2]), "=r"(r[3]) : "r"(addr));
}
__device__ __forceinline__ u32 packf16(float lo, float hi) {
    u32 r; asm("cvt.rn.f16x2.f32 %0, %1, %2;" : "=r"(r) : "f"(hi), "f"(lo)); return r;
}
// truncation split -> bf16x2 hi (exact prefix) + bf16x2 lo
__device__ __forceinline__ void split2(float a, float b, u32& hi, u32& lo) {
    u32 ua = __float_as_uint(a), ub = __float_as_uint(b);
    u32 h;
    asm("prmt.b32 %0, %1, %2, 0x7632;" : "=r"(h) : "r"(ua), "r"(ub));
    float ha = __uint_as_float(ua & 0xFFFF0000u);
    float hb = __uint_as_float(ub & 0xFFFF0000u);
    float la = a - ha, lb = b - hb;
    u32 l;
    asm("cvt.rn.bf16x2.f32 %0, %1, %2;" : "=r"(l) : "f"(lb), "f"(la));
    hi = h; lo = l;
}
__device__ __forceinline__ void cp_async16(u32 sdst, const void* gsrc) {
    asm volatile("cp.async.ca.shared.global [%0], [%1], 16;" :: "r"(sdst), "l"(gsrc));
}
__device__ __forceinline__ void cp_wait_all() {
    asm volatile("cp.async.commit_group;\n\tcp.async.wait_group 0;" ::: "memory");
}

// merged setup: W1 fp16 + W3 bf16 hi/lo + bias precompute (block 0)
__global__ void setup_kernel(const float* __restrict__ W1, const float* __restrict__ W3,
                             const float* __restrict__ b1, const float* __restrict__ b3) {
    for (int idx = blockIdx.x * blockDim.x + threadIdx.x;
         idx < 64 * 512 + 128 * 64; idx += gridDim.x * blockDim.x) {
        if (idx < 64 * 512) {
            int n = idx >> 9;
            float v = (n < HH) ? W1[(size_t)n * DIN + (idx & 511)] : 0.0f;
            g_w1f[idx] = __float2half_rn(v);
        } else {
            int i = idx - 64 * 512;
            int k = i & 63;
            float v = (k < HH) ? W3[(size_t)(i >> 6) * HH + k] : 0.0f;
            u32 uh = __float_as_uint(v) & 0xFFFF0000u;
            g_w3h[i] = __ushort_as_bfloat16((unsigned short)(uh >> 16));
            g_w3l[i] = __float2bfloat16(v - __uint_as_float(uh));
        }
    }
    if (blockIdx.x == 0) {
        __shared__ float s[256];
        int t = threadIdx.x;

        float v1 = (t < HH) ? b1[t] : 0.0f;
        s[t] = v1 * v1;
        __syncthreads();
        for (int o = 128; o > 0; o >>= 1) { if (t < o) s[t] += s[t + o]; __syncthreads(); }
        float nb2 = s[0];
        __syncthreads();
        {
            float nb = fmaxf(sqrtf(nb2), MINN);
            float th = tanhf(nb);
            float sc = th / nb;
            if (th > MAXN) { sc *= MAXN / th; th = MAXN; }
            if (t < HH) g_hb1[t] = sc * v1;
            if (t == 0) g_hb1sq = th * th;
        }

        float v3 = (t < DOUT) ? b3[t] : 0.0f;
        s[t] = v3 * v3;
        __syncthreads();
        for (int o = 128; o > 0; o >>= 1) { if (t < o) s[t] += s[t + o]; __syncthreads(); }
        nb2 = s[0];
        __syncthreads();
        {
            float nb = fmaxf(sqrtf(nb2), MINN);
            float th = tanhf(nb);
            float sc = th / nb;
            if (th > MAXN) { sc *= MAXN / th; th = MAXN; }
            if (t < DOUT) g_hb3[t] = sc * v3;
            if (t == 0) g_hb3sq = th * th;
        }
    }
}

extern __shared__ __align__(1024) char smraw[];

__global__ __launch_bounds__(TPB, 1)
void hnn_kernel(const float* __restrict__ X, float* __restrict__ out, int N, int nTiles)
{
    const u32 sb = (u32)__cvta_generic_to_shared(smraw);
    float* hb1s = (float*)(smraw + OFF_HB1);
    float* hb3s = (float*)(smraw + OFF_HB3);
    float* red  = (float*)(smraw + OFF_RED);
    float* x2s  = (float*)(smraw + OFF_X2S);
    float* un_s = (float*)(smraw + OFF_UNS);

    const int tid = threadIdx.x;
    const int lane = tid & 31;
    const int c = tid >> 5;           // warp 0..15
    const int mg = c & 3;             // GEMM1 row group (32 rows)
    const int ng = c >> 2;            // GEMM1 col group (16 cols)
    const int rq = lane >> 2;
    const int cq = lane & 3;
    const int cw = c & 7;             // GEMM2 row group (16 rows)
    const int ch = c >> 3;            // GEMM2 col half (64 cols)

    // resident staging: W1 fp16 (64x1040), W3 hi/lo, biases
    for (int u = tid; u < 4096; u += TPB) {
        int n = u >> 6, j = u & 63;
        cp_async16(sb + OFF_W1R + (u32)(n * 1040 + j * 16), g_w1f + n * 512 + j * 8);
    }
    for (int i = tid; i < 1024; i += TPB) {
        int n = i >> 3, j = i & 7;
        cp_async16(sb + OFF_W3H + (u32)(n * 144 + j * 16), g_w3h + n * 64 + j * 8);
        cp_async16(sb + OFF_W3L + (u32)(n * 144 + j * 16), g_w3l + n * 64 + j * 8);
    }
    for (int i = tid; i < 64; i += TPB) hb1s[i] = (i < HH) ? g_hb1[i] : 0.0f;
    if (tid < DOUT) hb3s[tid] = g_hb3[tid];
    const float hb1sq = g_hb1sq;
    const float hb3sq = g_hb3sq;
    cp_wait_all();
    __syncthreads();

    // GEMM1 B base address (W1 resident, 1040B row stride; ldsm pattern proven conflict-free)
    const u32 b1base = sb + OFF_W1R
        + (u32)((ng * 16 + ((lane >> 4) * 8) + (lane & 7)) * 1040 + ((lane >> 3) & 1) * 16);
    // GEMM2 lane addresses
    const u32 a2H = sb + OFF_UH + (u32)((cw * 16 + (lane & 15)) * 144 + (lane >> 4) * 16);
    const u32 a2L = a2H + 18432u;
    const u32 b2H = sb + OFF_W3H
        + (u32)((ch * 64 + (lane >> 4) * 8 + (lane & 7)) * 144 + ((lane >> 3) & 1) * 16);
    const u32 b2L = b2H + 18432u;

    // hb1 fragment values (2 n-tiles of 8 cols)
    float hb1v[4];
#pragma unroll
    for (int nt = 0; nt < 2; nt++) {
        float2 hv = *(float2*)(hb1s + ng * 16 + nt * 8 + cq * 2);
        hb1v[nt * 2] = hv.x; hb1v[nt * 2 + 1] = hv.y;
    }

    for (int tile = blockIdx.x; tile < nTiles; tile += gridDim.x) {
        const int baseRow = tile * MT;

        __syncthreads();   // prior tile fully done (U/red reads complete)

        // A-operand row pointers: rows mg*32 + j*8 + rq
        const float* prow[4];
#pragma unroll
        for (int j = 0; j < 4; j++) {
            int gr = baseRow + mg * 32 + j * 8 + rq;
            int grc = (gr < N) ? gr : (N - 1);
            prow[j] = X + (size_t)grc * DIN + 2 * cq;
        }

        float acc[2][2][4];
#pragma unroll
        for (int mt = 0; mt < 2; mt++)
#pragma unroll
            for (int nt = 0; nt < 2; nt++)
#pragma unroll
                for (int e = 0; e < 4; e++) acc[mt][nt][e] = 0.0f;
        float x2a = 0.0f;

        // preload step 0
        float2 v[8];
#pragma unroll
        for (int j = 0; j < 4; j++) {
            v[2 * j]     = *(const float2*)(prow[j]);
            v[2 * j + 1] = *(const float2*)(prow[j] + 8);
        }

        // -------- GEMM1: 32 k16 steps, BARRIER-FREE (W1 resident) --------
#pragma unroll 4
        for (int st = 0; st < 32; st++) {
            float2 vn[8];
            const bool last = (st == 31);
            if (!last) {
                const int noff = (st + 1) * 16;
#pragma unroll
                for (int j = 0; j < 4; j++) {
                    vn[2 * j]     = *(const float2*)(prow[j] + noff);
                    vn[2 * j + 1] = *(const float2*)(prow[j] + noff + 8);
                }
            }
            // x^2 partial: this warp owns row slot j = ng
            x2a = fmaf(v[2 * ng].x, v[2 * ng].x, x2a);
            x2a = fmaf(v[2 * ng].y, v[2 * ng].y, x2a);
            x2a = fmaf(v[2 * ng + 1].x, v[2 * ng + 1].x, x2a);
            x2a = fmaf(v[2 * ng + 1].y, v[2 * ng + 1].y, x2a);

            u32 ah[2][4];
            ah[0][0] = packf16(v[0].x, v[0].y);
            ah[0][1] = packf16(v[2].x, v[2].y);
            ah[0][2] = packf16(v[1].x, v[1].y);
            ah[0][3] = packf16(v[3].x, v[3].y);
            ah[1][0] = packf16(v[4].x, v[4].y);
            ah[1][1] = packf16(v[6].x, v[6].y);
            ah[1][2] = packf16(v[5].x, v[5].y);
            ah[1][3] = packf16(v[7].x, v[7].y);

            u32 bh[4];
            ldsm4(bh, b1base + (u32)(st * 32));
#pragma unroll
            for (int mt = 0; mt < 2; mt++)
#pragma unroll
                for (int nt = 0; nt < 2; nt++)
                    mma_f16(acc[mt][nt], ah[mt], bh + nt * 2);

            if (!last) {
#pragma unroll
                for (int j = 0; j < 8; j++) v[j] = vn[j];
            }
        }

        // -------- Epilogue 1, in fragments --------
        float S0[4], S1[4];
#pragma unroll
        for (int mt = 0; mt < 2; mt++)
#pragma unroll
            for (int h = 0; h < 2; h++) {
                int s = mt * 2 + h;
                float a0 = 0.f, a1 = 0.f;
#pragma unroll
                for (int nt = 0; nt < 2; nt++) {
                    float v0 = acc[mt][nt][2 * h], v1 = acc[mt][nt][2 * h + 1];
                    a0 = fmaf(v0, v0, fmaf(v1, v1, a0));
                    a1 = fmaf(v0, hb1v[2 * nt], fmaf(v1, hb1v[2 * nt + 1], a1));
                }
                S0[s] = a0; S1[s] = a1;
            }
#pragma unroll
        for (int s = 0; s < 4; s++) {
            S0[s] += __shfl_xor_sync(~0u, S0[s], 1);
            S0[s] += __shfl_xor_sync(~0u, S0[s], 2);
            S1[s] += __shfl_xor_sync(~0u, S1[s], 1);
            S1[s] += __shfl_xor_sync(~0u, S1[s], 2);
        }
        {
            float s2 = x2a;
            s2 += __shfl_xor_sync(0xffffffffu, s2, 1);
            s2 += __shfl_xor_sync(0xffffffffu, s2, 2);
            if (cq == 0) x2s[mg * 32 + ng * 8 + rq] = s2;
        }
        if (cq == 0) {
#pragma unroll
            for (int s = 0; s < 4; s++) {
                int row = mg * 32 + (s >> 1) * 16 + (s & 1) * 8 + rq;
                red[ng * 256 + row] = S0[s];
                red[ng * 256 + 128 + row] = S1[s];
            }
        }
        __syncthreads();
        float S0r[4], S1r[4], sx2v[4];
#pragma unroll
        for (int s = 0; s < 4; s++) {
            int row = mg * 32 + (s >> 1) * 16 + (s & 1) * 8 + rq;
            S0r[s] = (red[row] + red[256 + row]) + (red[512 + row] + red[768 + row]);
            S1r[s] = (red[128 + row] + red[384 + row]) + (red[640 + row] + red[896 + row]);
            sx2v[s] = x2s[row];
        }
        __syncthreads();

        float C1a[4], C2c[4];
#pragma unroll
        for (int s = 0; s < 4; s++) {
            float nx = fmaxf(sqrtf(sx2v[s]), MINN);
            float th = tanhf(nx);
            float al = th / nx;
            float xn1 = fmaxf(th, MINN);
            float p0 = al * al * S0r[s];
            float p1 = al * S1r[s];
            float mxn = fmaxf(sqrtf(p0), MINN);
            float art = artanh_c(xn1);
            float t = tanhf(mxn / xn1 * art);
            float g = t / mxn;
            float rn = t;
            if (rn > MAXN) { g *= MAXN / rn; rn = MAXN; }
            float xy = g * p1;
            float x2 = rn * rn;
            float den = fmaxf(1.0f + 2.0f * xy + x2 * hb1sq, MINN);
            float A = (1.0f + 2.0f * xy + hb1sq) / den;
            float B = (1.0f - x2) / den;
            float nv2 = A * A * x2 + 2.0f * A * B * xy + B * B * hb1sq;
            float nv = sqrtf(nv2);
            float pf = (nv > MAXN) ? (MAXN / nv) : 1.0f;
            nv = fminf(nv, MAXN);
            float beta = artanh_c(nv) / fmaxf(nv, MINN);
            C1a[s] = beta * pf * A * g * al;
            C2c[s] = beta * pf * B;
        }

        float Q[4] = {0.f, 0.f, 0.f, 0.f};
#pragma unroll
        for (int mt = 0; mt < 2; mt++)
#pragma unroll
            for (int nt = 0; nt < 2; nt++)
#pragma unroll
                for (int h = 0; h < 2; h++) {
                    int s = mt * 2 + h;
                    float xt0 = C1a[s] * acc[mt][nt][2 * h]     + C2c[s] * hb1v[2 * nt];
                    float xt1 = C1a[s] * acc[mt][nt][2 * h + 1] + C2c[s] * hb1v[2 * nt + 1];
                    xt0 = (xt0 > 0.0f) ? xt0 : 0.01f * xt0;
                    xt1 = (xt1 > 0.0f) ? xt1 : 0.01f * xt1;
                    acc[mt][nt][2 * h] = xt0;
                    acc[mt][nt][2 * h + 1] = xt1;
                    Q[s] = fmaf(xt0, xt0, fmaf(xt1, xt1, Q[s]));
                }
#pragma unroll
        for (int s = 0; s < 4; s++) {
            Q[s] += __shfl_xor_sync(~0u, Q[s], 1);
            Q[s] += __shfl_xor_sync(~0u, Q[s], 2);
        }
        if (cq == 0) {
#pragma unroll
            for (int s = 0; s < 4; s++) {
                int row = mg * 32 + (s >> 1) * 16 + (s & 1) * 8 + rq;
                red[ng * 128 + row] = Q[s];
            }
        }
        __syncthreads();
        float gam[4];
#pragma unroll
        for (int s = 0; s < 4; s++) {
            int row = mg * 32 + (s >> 1) * 16 + (s & 1) * 8 + rq;
            float q = (red[row] + red[128 + row]) + (red[256 + row] + red[384 + row]);
            float nxt = fmaxf(sqrtf(q), MINN);
            float t3 = tanhf(nxt);
            float gm = t3 / nxt;
            if (t3 > MAXN) { gm *= MAXN / t3; t3 = MAXN; }
            gam[s] = gm;
            if (ng == 0 && cq == 0) un_s[row] = fmaxf(t3, MINN);
        }

        // write u from fragments as bf16 hi/lo (ldmatrix layout)
#pragma unroll
        for (int mt = 0; mt < 2; mt++) {
            int r0 = mg * 32 + mt * 16 + rq;
#pragma unroll
            for (int nt = 0; nt < 2; nt++) {
                u32 coff = (u32)((ng * 16 + nt * 8 + cq * 2) * 2);
                u32 h, l;
                split2(gam[mt * 2] * acc[mt][nt][0], gam[mt * 2] * acc[mt][nt][1], h, l);
                *(u32*)(smraw + OFF_UH + r0 * 144 + coff) = h;
                *(u32*)(smraw + OFF_UL + r0 * 144 + coff) = l;
                split2(gam[mt * 2 + 1] * acc[mt][nt][2], gam[mt * 2 + 1] * acc[mt][nt][3], h, l);
                *(u32*)(smraw + OFF_UH + (r0 + 8) * 144 + coff) = h;
                *(u32*)(smraw + OFF_UL + (r0 + 8) * 144 + coff) = l;
            }
        }
        __syncthreads();

        // -------- GEMM2: u @ W3^T (bf16 3-way split; 16 rows x 64 cols per warp) --------
        float acc2[8][4];
#pragma unroll
        for (int nt = 0; nt < 8; nt++)
#pragma unroll
            for (int e = 0; e < 4; e++) acc2[nt][e] = 0.0f;

#pragma unroll
        for (int k16 = 0; k16 < 4; k16++) {
            u32 ah[4], al2[4];
            ldsm4(ah, a2H + (u32)(k16 * 32));
            ldsm4(al2, a2L + (u32)(k16 * 32));
#pragma unroll
            for (int np = 0; np < 4; np++) {
                u32 bh[4], bl[4];
                u32 boff = (u32)(np * 2304 + k16 * 32);
                ldsm4(bh, b2H + boff);
                ldsm4(bl, b2L + boff);
#pragma unroll
                for (int npi = 0; npi < 2; npi++) {
                    mma_bf16(acc2[np * 2 + npi], ah, bh + npi * 2);
                    mma_bf16(acc2[np * 2 + npi], al2, bh + npi * 2);
                    mma_bf16(acc2[np * 2 + npi], ah, bl + npi * 2);
                }
            }
        }

        // partial row sums over this warp's 64 cols
        float p0a = 0.f, p1a = 0.f, p0b = 0.f, p1b = 0.f;
#pragma unroll
        for (int nt = 0; nt < 8; nt++) {
            float2 hv = *(float2*)(hb3s + ch * 64 + nt * 8 + cq * 2);
            p0a = fmaf(acc2[nt][0], acc2[nt][0], fmaf(acc2[nt][1], acc2[nt][1], p0a));
            p1a = fmaf(acc2[nt][0], hv.x, fmaf(acc2[nt][1], hv.y, p1a));
            p0b = fmaf(acc2[nt][2], acc2[nt][2], fmaf(acc2[nt][3], acc2[nt][3], p0b));
            p1b = fmaf(acc2[nt][2], hv.x, fmaf(acc2[nt][3], hv.y, p1b));
        }
#pragma unroll
        for (int o = 1; o <= 2; o <<= 1) {
            p0a += __shfl_xor_sync(0xffffffffu, p0a, o);
            p1a += __shfl_xor_sync(0xffffffffu, p1a, o);
            p0b += __shfl_xor_sync(0xffffffffu, p0b, o);
            p1b += __shfl_xor_sync(0xffffffffu, p1b, o);
        }
        const int row1 = cw * 16 + rq;
        const int row2 = row1 + 8;
        if (cq == 0) {
            red[ch * 128 + row1] = p0a;
            red[ch * 128 + row2] = p0b;
            red[256 + ch * 128 + row1] = p1a;
            red[256 + ch * 128 + row2] = p1b;
        }
        __syncthreads();
        float p0t1 = red[row1] + red[128 + row1];
        float p1t1 = red[256 + row1] + red[384 + row1];
        float p0t2 = red[row2] + red[128 + row2];
        float p1t2 = red[256 + row2] + red[384 + row2];

        float cA1, cB1, cA2, cB2;
        {
            float un = un_s[row1];
            float mxn = fmaxf(sqrtf(p0t1), MINN);
            float art = artanh_c(un);
            float t = tanhf(mxn / un * art);
            float g = t / mxn;
            float rn = t;
            if (rn > MAXN) { g *= MAXN / rn; rn = MAXN; }
            float xy = g * p1t1;
            float x2 = rn * rn;
            float den = fmaxf(1.0f + 2.0f * xy + x2 * hb3sq, MINN);
            float A = (1.0f + 2.0f * xy + hb3sq) / den;
            float B = (1.0f - x2) / den;
            float nv = sqrtf(A * A * x2 + 2.0f * A * B * xy + B * B * hb3sq);
            float pf = (nv > MAXN) ? (MAXN / nv) : 1.0f;
            cA1 = pf * A * g; cB1 = pf * B;
        }
        {
            float un = un_s[row2];
            float mxn = fmaxf(sqrtf(p0t2), MINN);
            float art = artanh_c(un);
            float t = tanhf(mxn / un * art);
            float g = t / mxn;
            float rn = t;
            if (rn > MAXN) { g *= MAXN / rn; rn = MAXN; }
            float xy = g * p1t2;
            float x2 = rn * rn;
            float den = fmaxf(1.0f + 2.0f * xy + x2 * hb3sq, MINN);
            float A = (1.0f + 2.0f * xy + hb3sq) / den;
            float B = (1.0f - x2) / den;
            float nv = sqrtf(A * A * x2 + 2.0f * A * B * xy + B * B * hb3sq);
            float pf = (nv > MAXN) ? (MAXN / nv) : 1.0f;
            cA2 = pf * A * g; cB2 = pf * B;
        }

        {
            int g1r = baseRow + row1;
            int g2r = baseRow + row2;
            if (g1r < N) {
                float* o1 = out + (size_t)g1r * DOUT + ch * 64 + cq * 2;
#pragma unroll
                for (int nt = 0; nt < 8; nt++) {
                    float2 hv = *(float2*)(hb3s + ch * 64 + nt * 8 + cq * 2);
                    float2 vv;
                    vv.x = cA1 * acc2[nt][0] + cB1 * hv.x;
                    vv.y = cA1 * acc2[nt][1] + cB1 * hv.y;
                    *(float2*)(o1 + nt * 8) = vv;
                }
            }
            if (g2r < N) {
                float* o2 = out + (size_t)g2r * DOUT + ch * 64 + cq * 2;
#pragma unroll
                for (int nt = 0; nt < 8; nt++) {
                    float2 hv = *(float2*)(hb3s + ch * 64 + nt * 8 + cq * 2);
                    float2 vv;
                    vv.x = cA2 * acc2[nt][2] + cB2 * hv.x;
                    vv.y = cA2 * acc2[nt][3] + cB2 * hv.y;
                    *(float2*)(o2 + nt * 8) = vv;
                }
            }
        }
    }
}

extern "C" void kernel_launch(void* const* d_in, const int* in_sizes, int n_in,
                              void* d_out, int out_size) {
    const float* x  = (const float*)d_in[0];
    const float* W1 = (const float*)d_in[1];
    const float* b1 = (const float*)d_in[2];
    const float* W3 = (const float*)d_in[3];
    const float* b3 = (const float*)d_in[4];
    float* out = (float*)d_out;
    int N = in_sizes[0] / DIN;
    int nTiles = (N + MT - 1) / MT;
    int grid = nTiles < 148 ? nTiles : 148;

    cudaFuncSetAttribute(hnn_kernel, cudaFuncAttributeMaxDynamicSharedMemorySize, SMEM_BYTES);

    setup_kernel<<<161, 256>>>(W1, W3, b1, b3);
    hnn_kernel<<<grid, TPB, SMEM_BYTES>>>(x, out, N, nTiles);
}

// round 15
// speedup vs baseline: 2.2538x; 2.2538x over previous
#include <cuda_runtime.h>
#include <cuda_bf16.h>
#include <cuda_fp16.h>
#include <math.h>
#include <stdint.h>

#define TPB   256
#define MT    128
#define DIN   512
#define HH    50
#define DOUT  128
#define MAXN  0.996f
#define MINN  1e-15f

typedef unsigned long long ull;
typedef uint32_t u32;

// ---- smem byte offsets ----
#define OFF_W1R   0          // W1 fp16 resident: 64 rows x 1040B (512 fp16 + 16B pad)
#define OFF_W3F   66560      // W3 fp16 resident: 128 rows x 144B (64 fp16 + 16B pad)
#define OFF_UF    84992      // u fp16: 128 rows x 144B
#define OFF_RED   103424     // 512 f32 exchange
#define OFF_HB1   105472     // 64 f32
#define OFF_HB3   105728     // 128 f32
#define OFF_X2S   106240     // 128 f32
#define OFF_UNS   106752     // 128 f32
#define SMEM_BYTES 107264    // x2 CTAs = 214.5KB <= 227KB/SM -> 2 CTAs/SM

__device__ float g_hb1[64];
__device__ float g_hb3[128];
__device__ float g_hb1sq, g_hb3sq;
__device__ __align__(16) __half g_w1f[64 * 512];   // fp16 W1, rows 50..63 zero
__device__ __align__(16) __half g_w3f[128 * 64];   // fp16 W3, k 50..63 zero

__device__ __forceinline__ float artanh_c(float z) {
    z = fminf(z, 1.0f - 1e-7f);
    return 0.5f * logf((1.0f + z) / (1.0f - z));
}

// ---- MMA / async helpers ----
__device__ __forceinline__ void mma_f16(float* d, const u32* a, const u32* b) {
    asm("mma.sync.aligned.m16n8k16.row.col.f32.f16.f16.f32 "
        "{%0,%1,%2,%3}, {%4,%5,%6,%7}, {%8,%9}, {%0,%1,%2,%3};"
        : "+f"(d[0]), "+f"(d[1]), "+f"(d[2]), "+f"(d[3])
        : "r"(a[0]), "r"(a[1]), "r"(a[2]), "r"(a[3]), "r"(b[0]), "r"(b[1]));
}
__device__ __forceinline__ void ldsm4(u32* r, u32 addr) {
    asm volatile("ldmatrix.sync.aligned.m8n8.x4.shared.b16 {%0,%1,%2,%3}, [%4];"
        : "=r"(r[0]), "=r"(r[1]), "=r"(r[2]), "=r"(r[3]) : "r"(addr));
}
__device__ __forceinline__ u32 packf16(float lo, float hi) {
    u32 r; asm("cvt.rn.f16x2.f32 %0, %1, %2;" : "=r"(r) : "f"(hi), "f"(lo)); return r;
}
__device__ __forceinline__ void cp_async16(u32 sdst, const void* gsrc) {
    asm volatile("cp.async.ca.shared.global [%0], [%1], 16;" :: "r"(sdst), "l"(gsrc));
}
__device__ __forceinline__ void cp_wait_all() {
    asm volatile("cp.async.commit_group;\n\tcp.async.wait_group 0;" ::: "memory");
}

// merged setup: W1/W3 fp16 + bias precompute (block 0)
__global__ void setup_kernel(const float* __restrict__ W1, const float* __restrict__ W3,
                             const float* __restrict__ b1, const float* __restrict__ b3) {
    for (int idx = blockIdx.x * blockDim.x + threadIdx.x;
         idx < 64 * 512 + 128 * 64; idx += gridDim.x * blockDim.x) {
        if (idx < 64 * 512) {
            int n = idx >> 9;
            float v = (n < HH) ? W1[(size_t)n * DIN + (idx & 511)] : 0.0f;
            g_w1f[idx] = __float2half_rn(v);
        } else {
            int i = idx - 64 * 512;
            int k = i & 63;
            float v = (k < HH) ? W3[(size_t)(i >> 6) * HH + k] : 0.0f;
            g_w3f[i] = __float2half_rn(v);
        }
    }
    if (blockIdx.x == 0) {
        __shared__ float s[256];
        int t = threadIdx.x;

        float v1 = (t < HH) ? b1[t] : 0.0f;
        s[t] = v1 * v1;
        __syncthreads();
        for (int o = 128; o > 0; o >>= 1) { if (t < o) s[t] += s[t + o]; __syncthreads(); }
        float nb2 = s[0];
        __syncthreads();
        {
            float nb = fmaxf(sqrtf(nb2), MINN);
            float th = tanhf(nb);
            float sc = th / nb;
            if (th > MAXN) { sc *= MAXN / th; th = MAXN; }
            if (t < HH) g_hb1[t] = sc * v1;
            if (t == 0) g_hb1sq = th * th;
        }

        float v3 = (t < DOUT) ? b3[t] : 0.0f;
        s[t] = v3 * v3;
        __syncthreads();
        for (int o = 128; o > 0; o >>= 1) { if (t < o) s[t] += s[t + o]; __syncthreads(); }
        nb2 = s[0];
        __syncthreads();
        {
            float nb = fmaxf(sqrtf(nb2), MINN);
            float th = tanhf(nb);
            float sc = th / nb;
            if (th > MAXN) { sc *= MAXN / th; th = MAXN; }
            if (t < DOUT) g_hb3[t] = sc * v3;
            if (t == 0) g_hb3sq = th * th;
        }
    }
}

extern __shared__ __align__(1024) char smraw[];

__global__ __launch_bounds__(TPB, 2)
void hnn_kernel(const float* __restrict__ X, float* __restrict__ out, int N, int nTiles)
{
    const u32 sb = (u32)__cvta_generic_to_shared(smraw);
    float* hb1s = (float*)(smraw + OFF_HB1);
    float* hb3s = (float*)(smraw + OFF_HB3);
    float* red  = (float*)(smraw + OFF_RED);
    float* x2s  = (float*)(smraw + OFF_X2S);
    float* un_s = (float*)(smraw + OFF_UNS);

    const int tid = threadIdx.x;
    const int lane = tid & 31;
    const int c = tid >> 5;
    const int mg = c & 3;             // GEMM1 row group (32 rows)
    const int ng = c >> 2;            // GEMM1 col group (2 groups of 32 cols)
    const int rq = lane >> 2;
    const int cq = lane & 3;

    // resident staging: W1 fp16 (64x1040), W3 fp16 (128x144), biases
    for (int u = tid; u < 4096; u += TPB) {
        int n = u >> 6, j = u & 63;
        cp_async16(sb + OFF_W1R + (u32)(n * 1040 + j * 16), g_w1f + n * 512 + j * 8);
    }
    for (int i = tid; i < 1024; i += TPB) {
        int n = i >> 3, j = i & 7;
        cp_async16(sb + OFF_W3F + (u32)(n * 144 + j * 16), g_w3f + n * 64 + j * 8);
    }
    for (int i = tid; i < 64; i += TPB) hb1s[i] = (i < HH) ? g_hb1[i] : 0.0f;
    if (tid < DOUT) hb3s[tid] = g_hb3[tid];
    const float hb1sq = g_hb1sq;
    const float hb3sq = g_hb3sq;
    cp_wait_all();
    __syncthreads();

    // GEMM1 B lane base (resident W1, 1040B stride; r*260 mod 32 = 4r -> conflict-free)
    const u32 bN   = (u32)(ng * 32 + ((lane >> 4) * 8) + (lane & 7));
    const u32 bKof = (u32)(((lane >> 3) & 1) * 16);
    const u32 b1base = sb + OFF_W1R + bN * 1040u + bKof;
    // GEMM2 lane addresses (fp16 single)
    const u32 a2F = sb + OFF_UF + (u32)((c * 16 + (lane & 15)) * 144 + (lane >> 4) * 16);
    const u32 b2F = sb + OFF_W3F + (u32)((((lane >> 4) * 8) + (lane & 7)) * 144 + ((lane >> 3) & 1) * 16);

    // hb1 fragment values for this warp's 32 cols
    float hb1v[8];
#pragma unroll
    for (int nt = 0; nt < 4; nt++) {
        float2 hv = *(float2*)(hb1s + ng * 32 + nt * 8 + cq * 2);
        hb1v[nt * 2] = hv.x; hb1v[nt * 2 + 1] = hv.y;
    }

    for (int tile = blockIdx.x; tile < nTiles; tile += gridDim.x) {
        const int baseRow = tile * MT;

        __syncthreads();   // prior tile fully done (U reads complete)

        // A-operand row pointers: rows mg*32 + j*8 + rq
        const float* prow[4];
#pragma unroll
        for (int j = 0; j < 4; j++) {
            int gr = baseRow + mg * 32 + j * 8 + rq;
            int grc = (gr < N) ? gr : (N - 1);
            prow[j] = X + (size_t)grc * DIN + 2 * cq;
        }

        float acc[2][4][4];
#pragma unroll
        for (int mt = 0; mt < 2; mt++)
#pragma unroll
            for (int nt = 0; nt < 4; nt++)
#pragma unroll
                for (int e = 0; e < 4; e++) acc[mt][nt][e] = 0.0f;
        float x2a[4] = {0.f, 0.f, 0.f, 0.f};

        // preload step 0
        float2 v[8];
#pragma unroll
        for (int j = 0; j < 4; j++) {
            v[2 * j]     = *(const float2*)(prow[j]);
            v[2 * j + 1] = *(const float2*)(prow[j] + 8);
        }

        // -------- GEMM1: 32 k16 steps, BARRIER-FREE (W1 resident fp16) --------
#pragma unroll 4
        for (int st = 0; st < 32; st++) {
            float2 vn[8];
            const bool last = (st == 31);
            if (!last) {
                const int noff = (st + 1) * 16;
#pragma unroll
                for (int j = 0; j < 4; j++) {
                    vn[2 * j]     = *(const float2*)(prow[j] + noff);
                    vn[2 * j + 1] = *(const float2*)(prow[j] + noff + 8);
                }
            }
            if (ng == 0) {
#pragma unroll
                for (int j = 0; j < 4; j++) {
                    x2a[j] = fmaf(v[2 * j].x, v[2 * j].x, x2a[j]);
                    x2a[j] = fmaf(v[2 * j].y, v[2 * j].y, x2a[j]);
                    x2a[j] = fmaf(v[2 * j + 1].x, v[2 * j + 1].x, x2a[j]);
                    x2a[j] = fmaf(v[2 * j + 1].y, v[2 * j + 1].y, x2a[j]);
                }
            }
            u32 ah[2][4];
            ah[0][0] = packf16(v[0].x, v[0].y);
            ah[0][1] = packf16(v[2].x, v[2].y);
            ah[0][2] = packf16(v[1].x, v[1].y);
            ah[0][3] = packf16(v[3].x, v[3].y);
            ah[1][0] = packf16(v[4].x, v[4].y);
            ah[1][1] = packf16(v[6].x, v[6].y);
            ah[1][2] = packf16(v[5].x, v[5].y);
            ah[1][3] = packf16(v[7].x, v[7].y);

            u32 bh[8];
            ldsm4(bh,     b1base + (u32)(st * 32));
            ldsm4(bh + 4, b1base + 16640u + (u32)(st * 32));   // +16 rows * 1040B
#pragma unroll
            for (int mt = 0; mt < 2; mt++)
#pragma unroll
                for (int nt = 0; nt < 4; nt++)
                    mma_f16(acc[mt][nt], ah[mt], bh + nt * 2);

            if (!last) {
#pragma unroll
                for (int j = 0; j < 8; j++) v[j] = vn[j];
            }
        }

        // -------- Epilogue 1, in fragments --------
        float S0[4], S1[4];
#pragma unroll
        for (int mt = 0; mt < 2; mt++)
#pragma unroll
            for (int h = 0; h < 2; h++) {
                int s = mt * 2 + h;
                float a0 = 0.f, a1 = 0.f;
#pragma unroll
                for (int nt = 0; nt < 4; nt++) {
                    float v0 = acc[mt][nt][2 * h], v1 = acc[mt][nt][2 * h + 1];
                    a0 = fmaf(v0, v0, fmaf(v1, v1, a0));
                    a1 = fmaf(v0, hb1v[2 * nt], fmaf(v1, hb1v[2 * nt + 1], a1));
                }
                S0[s] = a0; S1[s] = a1;
            }
#pragma unroll
        for (int s = 0; s < 4; s++) {
            S0[s] += __shfl_xor_sync(~0u, S0[s], 1);
            S0[s] += __shfl_xor_sync(~0u, S0[s], 2);
            S1[s] += __shfl_xor_sync(~0u, S1[s], 1);
            S1[s] += __shfl_xor_sync(~0u, S1[s], 2);
        }
        if (ng == 0) {
#pragma unroll
            for (int h = 0; h < 4; h++) {
                float s2 = x2a[h];
                s2 += __shfl_xor_sync(0xffffffffu, s2, 1);
                s2 += __shfl_xor_sync(0xffffffffu, s2, 2);
                if (cq == 0) x2s[mg * 32 + h * 8 + rq] = s2;
            }
        }
        if (cq == 0) {
#pragma unroll
            for (int s = 0; s < 4; s++) {
                int row = mg * 32 + (s >> 1) * 16 + (s & 1) * 8 + rq;
                red[ng * 256 + row] = S0[s];
                red[ng * 256 + 128 + row] = S1[s];
            }
        }
        __syncthreads();
        float S0r[4], S1r[4], sx2v[4];
#pragma unroll
        for (int s = 0; s < 4; s++) {
            int row = mg * 32 + (s >> 1) * 16 + (s & 1) * 8 + rq;
            S0r[s] = red[row] + red[256 + row];
            S1r[s] = red[128 + row] + red[384 + row];
            sx2v[s] = x2s[row];
        }
        __syncthreads();

        float C1a[4], C2c[4];
#pragma unroll
        for (int s = 0; s < 4; s++) {
            float nx = fmaxf(sqrtf(sx2v[s]), MINN);
            float th = tanhf(nx);
            float al = th / nx;
            float xn1 = fmaxf(th, MINN);
            float p0 = al * al * S0r[s];
            float p1 = al * S1r[s];
            float mxn = fmaxf(sqrtf(p0), MINN);
            float art = artanh_c(xn1);
            float t = tanhf(mxn / xn1 * art);
            float g = t / mxn;
            float rn = t;
            if (rn > MAXN) { g *= MAXN / rn; rn = MAXN; }
            float xy = g * p1;
            float x2 = rn * rn;
            float den = fmaxf(1.0f + 2.0f * xy + x2 * hb1sq, MINN);
            float A = (1.0f + 2.0f * xy + hb1sq) / den;
            float B = (1.0f - x2) / den;
            float nv2 = A * A * x2 + 2.0f * A * B * xy + B * B * hb1sq;
            float nv = sqrtf(nv2);
            float pf = (nv > MAXN) ? (MAXN / nv) : 1.0f;
            nv = fminf(nv, MAXN);
            float beta = artanh_c(nv) / fmaxf(nv, MINN);
            C1a[s] = beta * pf * A * g * al;
            C2c[s] = beta * pf * B;
        }

        float Q[4] = {0.f, 0.f, 0.f, 0.f};
#pragma unroll
        for (int mt = 0; mt < 2; mt++)
#pragma unroll
            for (int nt = 0; nt < 4; nt++)
#pragma unroll
                for (int h = 0; h < 2; h++) {
                    int s = mt * 2 + h;
                    float xt0 = C1a[s] * acc[mt][nt][2 * h]     + C2c[s] * hb1v[2 * nt];
                    float xt1 = C1a[s] * acc[mt][nt][2 * h + 1] + C2c[s] * hb1v[2 * nt + 1];
                    xt0 = (xt0 > 0.0f) ? xt0 : 0.01f * xt0;
                    xt1 = (xt1 > 0.0f) ? xt1 : 0.01f * xt1;
                    acc[mt][nt][2 * h] = xt0;
                    acc[mt][nt][2 * h + 1] = xt1;
                    Q[s] = fmaf(xt0, xt0, fmaf(xt1, xt1, Q[s]));
                }
#pragma unroll
        for (int s = 0; s < 4; s++) {
            Q[s] += __shfl_xor_sync(~0u, Q[s], 1);
            Q[s] += __shfl_xor_sync(~0u, Q[s], 2);
        }
        if (cq == 0) {
#pragma unroll
            for (int s = 0; s < 4; s++) {
                int row = mg * 32 + (s >> 1) * 16 + (s & 1) * 8 + rq;
                red[ng * 128 + row] = Q[s];
            }
        }
        __syncthreads();
        float gam[4];
#pragma unroll
        for (int s = 0; s < 4; s++) {
            int row = mg * 32 + (s >> 1) * 16 + (s & 1) * 8 + rq;
            float q = red[row] + red[128 + row];
            float nxt = fmaxf(sqrtf(q), MINN);
            float t3 = tanhf(nxt);
            float gm = t3 / nxt;
            if (t3 > MAXN) { gm *= MAXN / t3; t3 = MAXN; }
            gam[s] = gm;
            if (ng == 0 && cq == 0) un_s[row] = fmaxf(t3, MINN);
        }

        // write u = gam * xt from fragments as single fp16 (ldmatrix layout)
#pragma unroll
        for (int mt = 0; mt < 2; mt++) {
            int r0 = mg * 32 + mt * 16 + rq;
#pragma unroll
            for (int nt = 0; nt < 4; nt++) {
                u32 coff = (u32)((ng * 32 + nt * 8 + cq * 2) * 2);
                *(u32*)(smraw + OFF_UF + r0 * 144 + coff) =
                    packf16(gam[mt * 2] * acc[mt][nt][0], gam[mt * 2] * acc[mt][nt][1]);
                *(u32*)(smraw + OFF_UF + (r0 + 8) * 144 + coff) =
                    packf16(gam[mt * 2 + 1] * acc[mt][nt][2], gam[mt * 2 + 1] * acc[mt][nt][3]);
            }
        }
        __syncthreads();

        // -------- GEMM2: u @ W3^T (fp16 single-pass; 16 rows/warp, 128 cols) --------
        float acc2[16][4];
#pragma unroll
        for (int nt = 0; nt < 16; nt++)
#pragma unroll
            for (int e = 0; e < 4; e++) acc2[nt][e] = 0.0f;

#pragma unroll
        for (int k16 = 0; k16 < 4; k16++) {
            u32 ah[4];
            ldsm4(ah, a2F + (u32)(k16 * 32));
#pragma unroll
            for (int np = 0; np < 8; np++) {
                u32 bh[4];
                ldsm4(bh, b2F + (u32)(np * 2304 + k16 * 32));
#pragma unroll
                for (int npi = 0; npi < 2; npi++)
                    mma_f16(acc2[np * 2 + npi], ah, bh + npi * 2);
            }
        }

        float p0a = 0.f, p1a = 0.f, p0b = 0.f, p1b = 0.f;
#pragma unroll
        for (int nt = 0; nt < 16; nt++) {
            float2 hv = *(float2*)(hb3s + nt * 8 + cq * 2);
            p0a = fmaf(acc2[nt][0], acc2[nt][0], fmaf(acc2[nt][1], acc2[nt][1], p0a));
            p1a = fmaf(acc2[nt][0], hv.x, fmaf(acc2[nt][1], hv.y, p1a));
            p0b = fmaf(acc2[nt][2], acc2[nt][2], fmaf(acc2[nt][3], acc2[nt][3], p0b));
            p1b = fmaf(acc2[nt][2], hv.x, fmaf(acc2[nt][3], hv.y, p1b));
        }
#pragma unroll
        for (int o = 1; o <= 2; o <<= 1) {
            p0a += __shfl_xor_sync(0xffffffffu, p0a, o);
            p1a += __shfl_xor_sync(0xffffffffu, p1a, o);
            p0b += __shfl_xor_sync(0xffffffffu, p0b, o);
            p1b += __shfl_xor_sync(0xffffffffu, p1b, o);
        }

        const int row1 = c * 16 + rq;
        const int row2 = row1 + 8;
        float cA1, cB1, cA2, cB2;
        {
            float un = un_s[row1];
            float mxn = fmaxf(sqrtf(p0a), MINN);
            float art = artanh_c(un);
            float t = tanhf(mxn / un * art);
            float g = t / mxn;
            float rn = t;
            if (rn > MAXN) { g *= MAXN / rn; rn = MAXN; }
            float xy = g * p1a;
            float x2 = rn * rn;
            float den = fmaxf(1.0f + 2.0f * xy + x2 * hb3sq, MINN);
            float A = (1.0f + 2.0f * xy + hb3sq) / den;
            float B = (1.0f - x2) / den;
            float nv = sqrtf(A * A * x2 + 2.0f * A * B * xy + B * B * hb3sq);
            float pf = (nv > MAXN) ? (MAXN / nv) : 1.0f;
            cA1 = pf * A * g; cB1 = pf * B;
        }
        {
            float un = un_s[row2];
            float mxn = fmaxf(sqrtf(p0b), MINN);
            float art = artanh_c(un);
            float t = tanhf(mxn / un * art);
            float g = t / mxn;
            float rn = t;
            if (rn > MAXN) { g *= MAXN / rn; rn = MAXN; }
            float xy = g * p1b;
            float x2 = rn * rn;
            float den = fmaxf(1.0f + 2.0f * xy + x2 * hb3sq, MINN);
            float A = (1.0f + 2.0f * xy + hb3sq) / den;
            float B = (1.0f - x2) / den;
            float nv = sqrtf(A * A * x2 + 2.0f * A * B * xy + B * B * hb3sq);
            float pf = (nv > MAXN) ? (MAXN / nv) : 1.0f;
            cA2 = pf * A * g; cB2 = pf * B;
        }

        {
            int g1r = baseRow + row1;
            int g2r = baseRow + row2;
            if (g1r < N) {
                float* o1 = out + (size_t)g1r * DOUT + cq * 2;
#pragma unroll
                for (int nt = 0; nt < 16; nt++) {
                    float2 hv = *(float2*)(hb3s + nt * 8 + cq * 2);
                    float2 vv;
                    vv.x = cA1 * acc2[nt][0] + cB1 * hv.x;
                    vv.y = cA1 * acc2[nt][1] + cB1 * hv.y;
                    *(float2*)(o1 + nt * 8) = vv;
                }
            }
            if (g2r < N) {
                float* o2 = out + (size_t)g2r * DOUT + cq * 2;
#pragma unroll
                for (int nt = 0; nt < 16; nt++) {
                    float2 hv = *(float2*)(hb3s + nt * 8 + cq * 2);
                    float2 vv;
                    vv.x = cA2 * acc2[nt][2] + cB2 * hv.x;
                    vv.y = cA2 * acc2[nt][3] + cB2 * hv.y;
                    *(float2*)(o2 + nt * 8) = vv;
                }
            }
        }
    }
}

extern "C" void kernel_launch(void* const* d_in, const int* in_sizes, int n_in,
                              void* d_out, int out_size) {
    const float* x  = (const float*)d_in[0];
    const float* W1 = (const float*)d_in[1];
    const float* b1 = (const float*)d_in[2];
    const float* W3 = (const float*)d_in[3];
    const float* b3 = (const float*)d_in[4];
    float* out = (float*)d_out;
    int N = in_sizes[0] / DIN;
    int nTiles = (N + MT - 1) / MT;
    int grid = nTiles < 296 ? nTiles : 296;

    cudaFuncSetAttribute(hnn_kernel, cudaFuncAttributeMaxDynamicSharedMemorySize, SMEM_BYTES);

    setup_kernel<<<161, 256>>>(W1, W3, b1, b3);
    hnn_kernel<<<grid, TPB, SMEM_BYTES>>>(x, out, N, nTiles);
}